// round 1
// baseline (speedup 1.0000x reference)
#include <cuda_runtime.h>
#include <math.h>

#define BATCH 2
#define DIM   48
#define HEADS 8
#define CPH   6          // channels per head
#define HH    384
#define WW    384
#define NPIX  (HH*WW)    // 147456

// depthwise tile
#define TX  32
#define TY  8
#define HLX 34
#define HLY 10
#define HL  (HLX*HLY)    // 340

// ---------------- scratch (static device globals: allowed) ----------------
__device__ float g_pwq [BATCH*DIM*NPIX];     // 56.6 MB
__device__ float g_pwkv[BATCH*2*DIM*NPIX];   // 113 MB
__device__ float g_v   [BATCH*DIM*NPIX];     // 56.6 MB
__device__ float g_acc [BATCH*HEADS*48];     // per (b,h): 36 Gram + 6 |q|^2 + 6 |k|^2
__device__ float g_meff[BATCH*DIM*DIM];      // folded Wout @ blockdiag(attn)

// ---------------- packed f32x2 helpers (Blackwell FFMA2) ----------------
__device__ __forceinline__ unsigned long long pk2(float lo, float hi){
    unsigned long long r;
    asm("mov.b64 %0, {%1,%2};" : "=l"(r) : "f"(lo), "f"(hi));
    return r;
}
__device__ __forceinline__ void fma2(unsigned long long &d,
                                     unsigned long long a,
                                     unsigned long long b){
    asm("fma.rn.f32x2 %0, %1, %2, %3;" : "=l"(d) : "l"(a), "l"(b), "l"(d));
}
__device__ __forceinline__ float2 unpk(unsigned long long v){
    float lo, hi;
    asm("mov.b64 {%0,%1}, %2;" : "=f"(lo), "=f"(hi) : "l"(v));
    return make_float2(lo, hi);
}

// ---------------- kernels ----------------
__global__ void zero_acc_kernel(){
    int t = blockIdx.x*blockDim.x + threadIdx.x;
    if (t < BATCH*HEADS*48) g_acc[t] = 0.f;
}

// out[b, oc, n] = sum_ic W[b?][oc][ic] * in[b, ic, n]   (1x1 conv as GEMM)
// 128 pixels per block, 256 threads: 32 pixel-quads x 8 oc-groups.
// FFMA2 packs 2 pixels per instruction.
template<int OC>
__global__ __launch_bounds__(256) void pw_kernel(const float* __restrict__ in,
                                                 const float* __restrict__ W,
                                                 float* __restrict__ out,
                                                 int wPerBatch){
    __shared__ unsigned long long ws[OC*DIM];
    const int b = blockIdx.y;
    const float* Wb = W + b*wPerBatch;
    for (int t = threadIdx.x; t < OC*DIM; t += 256){
        float w = Wb[t];
        ws[t] = pk2(w, w);
    }
    __syncthreads();

    const int tid = threadIdx.x;
    const int pxq = tid & 31;        // pixel quad id (4 px each -> 128 px)
    const int ocg = tid >> 5;        // 8 oc groups (one warp per group)
    constexpr int OCT = OC/8;        // oc per thread: 6 or 12
    const int base = blockIdx.x*128 + pxq*4;
    const float* inp = in + (size_t)b*DIM*NPIX + base;

    unsigned long long acc[OCT][2];
    #pragma unroll
    for (int j = 0; j < OCT; j++){ acc[j][0] = 0ull; acc[j][1] = 0ull; }

    #pragma unroll 4
    for (int ic = 0; ic < DIM; ic++){
        float4 x = *reinterpret_cast<const float4*>(inp + (size_t)ic*NPIX);
        unsigned long long x01 = pk2(x.x, x.y);
        unsigned long long x23 = pk2(x.z, x.w);
        #pragma unroll
        for (int j = 0; j < OCT; j++){
            unsigned long long w = ws[(ocg*OCT + j)*DIM + ic];
            fma2(acc[j][0], x01, w);
            fma2(acc[j][1], x23, w);
        }
    }

    float* op = out + (size_t)b*OC*NPIX + base;
    #pragma unroll
    for (int j = 0; j < OCT; j++){
        float2 lo = unpk(acc[j][0]);
        float2 hi = unpk(acc[j][1]);
        float4 o = make_float4(lo.x, lo.y, hi.x, hi.y);
        *reinterpret_cast<float4*>(op + (size_t)(ocg*OCT + j)*NPIX) = o;
    }
}

// Depthwise 3x3 (middle kd slice) for q,k,v + Gram/norm reduction + v store.
// Block: 256 threads = 32 lanes (x) * 8 warps (one head per warp).
// Each thread covers one x-column of an 8-row tile for its head's 6 channels.
__global__ __launch_bounds__(256) void dw_kernel(const float* __restrict__ Wq2,
                                                 const float* __restrict__ Wkv2){
    extern __shared__ float sm[];
    float* sq  = sm;                  // DIM  * HL
    float* skv = sm + DIM*HL;         // 2DIM * HL
    float* w2  = sm + 3*DIM*HL;       // 48*9 (q) + 96*9 (kv) = 1296

    const int b   = blockIdx.z;
    const int x0  = blockIdx.x*TX;
    const int y0  = blockIdx.y*TY;
    const int tid = threadIdx.x;

    // weights: mid kd slice of (C,1,3,3,3) -> c*27 + 9 + kh*3 + kw
    for (int t = tid; t < DIM*9;   t += 256) w2[t]       = Wq2 [(t/9)*27 + 9 + (t%9)];
    for (int t = tid; t < 2*DIM*9; t += 256) w2[432 + t] = Wkv2[(t/9)*27 + 9 + (t%9)];

    // halo staging (zero padding outside image)
    const float* pq = g_pwq + (size_t)b*DIM*NPIX;
    for (int e = tid; e < DIM*HL; e += 256){
        int c = e/HL, rem = e%HL, r = rem/HLX, col = rem%HLX;
        int yy = y0 - 1 + r, xx = x0 - 1 + col;
        float v = 0.f;
        if (yy >= 0 && yy < HH && xx >= 0 && xx < WW)
            v = pq[(size_t)c*NPIX + yy*WW + xx];
        sq[e] = v;
    }
    const float* pkv = g_pwkv + (size_t)b*2*DIM*NPIX;
    for (int e = tid; e < 2*DIM*HL; e += 256){
        int c = e/HL, rem = e%HL, r = rem/HLX, col = rem%HLX;
        int yy = y0 - 1 + r, xx = x0 - 1 + col;
        float v = 0.f;
        if (yy >= 0 && yy < HH && xx >= 0 && xx < WW)
            v = pkv[(size_t)c*NPIX + yy*WW + xx];
        skv[e] = v;
    }
    __syncthreads();

    const int lane = tid & 31;
    const int h    = tid >> 5;

    float ka[CPH][TY];
    float kn[CPH], qn[CPH], G[CPH*CPH];
    #pragma unroll
    for (int i = 0; i < CPH; i++){ kn[i] = 0.f; qn[i] = 0.f; }
    #pragma unroll
    for (int i = 0; i < CPH*CPH; i++) G[i] = 0.f;

    // ---- k streams (kept in registers for Gram) ----
    #pragma unroll
    for (int c6 = 0; c6 < CPH; c6++){
        int c = h*CPH + c6;
        const float* base = skv + c*HL + lane;
        float d0[HLY], d1[HLY], d2[HLY];
        #pragma unroll
        for (int r = 0; r < HLY; r++){
            d0[r] = base[r*HLX]; d1[r] = base[r*HLX+1]; d2[r] = base[r*HLX+2];
        }
        float wr[9];
        #pragma unroll
        for (int t = 0; t < 9; t++) wr[t] = w2[432 + c*9 + t];
        #pragma unroll
        for (int i = 0; i < TY; i++){
            float s = wr[0]*d0[i]   + wr[1]*d1[i]   + wr[2]*d2[i]
                    + wr[3]*d0[i+1] + wr[4]*d1[i+1] + wr[5]*d2[i+1]
                    + wr[6]*d0[i+2] + wr[7]*d1[i+2] + wr[8]*d2[i+2];
            ka[c6][i] = s;
            kn[c6] += s*s;
        }
    }
    // ---- q streams: accumulate Gram immediately ----
    #pragma unroll
    for (int c6 = 0; c6 < CPH; c6++){
        int c = h*CPH + c6;
        const float* base = sq + c*HL + lane;
        float d0[HLY], d1[HLY], d2[HLY];
        #pragma unroll
        for (int r = 0; r < HLY; r++){
            d0[r] = base[r*HLX]; d1[r] = base[r*HLX+1]; d2[r] = base[r*HLX+2];
        }
        float wr[9];
        #pragma unroll
        for (int t = 0; t < 9; t++) wr[t] = w2[c*9 + t];
        float qrow[TY];
        #pragma unroll
        for (int i = 0; i < TY; i++){
            float s = wr[0]*d0[i]   + wr[1]*d1[i]   + wr[2]*d2[i]
                    + wr[3]*d0[i+1] + wr[4]*d1[i+1] + wr[5]*d2[i+1]
                    + wr[6]*d0[i+2] + wr[7]*d1[i+2] + wr[8]*d2[i+2];
            qrow[i] = s;
            qn[c6] += s*s;
        }
        #pragma unroll
        for (int d6 = 0; d6 < CPH; d6++){
            float s = 0.f;
            #pragma unroll
            for (int i = 0; i < TY; i++) s += qrow[i]*ka[d6][i];
            G[c6*CPH + d6] += s;
        }
    }
    // ---- v streams: compute and store ----
    float* vo = g_v + (size_t)b*DIM*NPIX;
    #pragma unroll
    for (int c6 = 0; c6 < CPH; c6++){
        int c = h*CPH + c6;
        const float* base = skv + (DIM + c)*HL + lane;
        float d0[HLY], d1[HLY], d2[HLY];
        #pragma unroll
        for (int r = 0; r < HLY; r++){
            d0[r] = base[r*HLX]; d1[r] = base[r*HLX+1]; d2[r] = base[r*HLX+2];
        }
        float wr[9];
        #pragma unroll
        for (int t = 0; t < 9; t++) wr[t] = w2[432 + (DIM + c)*9 + t];
        #pragma unroll
        for (int i = 0; i < TY; i++){
            float s = wr[0]*d0[i]   + wr[1]*d1[i]   + wr[2]*d2[i]
                    + wr[3]*d0[i+1] + wr[4]*d1[i+1] + wr[5]*d2[i+1]
                    + wr[6]*d0[i+2] + wr[7]*d1[i+2] + wr[8]*d2[i+2];
            vo[(size_t)c*NPIX + (size_t)(y0+i)*WW + x0 + lane] = s;
        }
    }

    // ---- warp reduce (one head per warp) + global atomics ----
    float* accb = g_acc + (b*HEADS + h)*48;
    #pragma unroll
    for (int j = 0; j < CPH*CPH; j++){
        float v = G[j];
        #pragma unroll
        for (int o = 16; o; o >>= 1) v += __shfl_xor_sync(0xffffffffu, v, o);
        if (lane == 0) atomicAdd(&accb[j], v);
    }
    #pragma unroll
    for (int j = 0; j < CPH; j++){
        float v = qn[j];
        #pragma unroll
        for (int o = 16; o; o >>= 1) v += __shfl_xor_sync(0xffffffffu, v, o);
        if (lane == 0) atomicAdd(&accb[36 + j], v);
        float u = kn[j];
        #pragma unroll
        for (int o = 16; o; o >>= 1) u += __shfl_xor_sync(0xffffffffu, u, o);
        if (lane == 0) atomicAdd(&accb[42 + j], u);
    }
}

// softmax(G / (|q||k|) * temp) per (b,h), then fold with Wout into Meff[b] (48x48).
__global__ void attn_kernel(const float* __restrict__ Wout,
                            const float* __restrict__ temp){
    __shared__ float attn_s[BATCH*HEADS*36];
    int t = threadIdx.x;
    if (t < BATCH*HEADS*CPH){                      // 96 rows
        int b  = t/(HEADS*CPH);
        int h  = (t/CPH)%HEADS;
        int c6 = t%CPH;
        const float* a = g_acc + (b*HEADS + h)*48;
        float qnorm = fmaxf(sqrtf(a[36 + c6]), 1e-12f);
        float s[CPH];
        float mx = -1e30f;
        #pragma unroll
        for (int d6 = 0; d6 < CPH; d6++){
            float knorm = fmaxf(sqrtf(a[42 + d6]), 1e-12f);
            float v = a[c6*CPH + d6] / (qnorm*knorm) * temp[h];
            s[d6] = v;
            mx = fmaxf(mx, v);
        }
        float sum = 0.f;
        #pragma unroll
        for (int d6 = 0; d6 < CPH; d6++){ s[d6] = expf(s[d6]-mx); sum += s[d6]; }
        float inv = 1.f/sum;
        #pragma unroll
        for (int d6 = 0; d6 < CPH; d6++)
            attn_s[(b*HEADS + h)*36 + c6*CPH + d6] = s[d6]*inv;
    }
    __syncthreads();
    // Meff[b][o][d] = sum_c6 Wout[o][h*6+c6] * attn[b][h][c6][d6],  h=d/6
    for (int e = t; e < BATCH*DIM*DIM; e += blockDim.x){
        int b = e/(DIM*DIM), rem = e%(DIM*DIM), o = rem/DIM, d = rem%DIM;
        int h = d/CPH, d6 = d%CPH;
        float s = 0.f;
        #pragma unroll
        for (int c6 = 0; c6 < CPH; c6++)
            s += Wout[o*DIM + h*CPH + c6] * attn_s[(b*HEADS + h)*36 + c6*CPH + d6];
        g_meff[e] = s;
    }
}

// ---------------- launch ----------------
extern "C" void kernel_launch(void* const* d_in, const int* in_sizes, int n_in,
                              void* d_out, int out_size){
    const float* img  = (const float*)d_in[0];
    const float* evs  = (const float*)d_in[1];
    const float* Wq1  = (const float*)d_in[2];
    const float* Wq2  = (const float*)d_in[3];
    const float* Wkv1 = (const float*)d_in[4];
    const float* Wkv2 = (const float*)d_in[5];
    const float* Wout = (const float*)d_in[6];
    const float* temp = (const float*)d_in[7];
    float* out = (float*)d_out;

    float *pwq, *pwkv, *v, *meff;
    cudaGetSymbolAddress((void**)&pwq,  g_pwq);
    cudaGetSymbolAddress((void**)&pwkv, g_pwkv);
    cudaGetSymbolAddress((void**)&v,    g_v);
    cudaGetSymbolAddress((void**)&meff, g_meff);

    size_t smem = (size_t)(3*DIM*HL + 3*DIM*9) * sizeof(float);  // 201,024 B
    cudaFuncSetAttribute(dw_kernel, cudaFuncAttributeMaxDynamicSharedMemorySize, (int)smem);

    zero_acc_kernel<<<3, 256>>>();

    dim3 gpw(NPIX/128, BATCH);
    pw_kernel<DIM>  <<<gpw, 256>>>(evs, Wq1,  pwq,  0);
    pw_kernel<2*DIM><<<gpw, 256>>>(img, Wkv1, pwkv, 0);

    dim3 gdw(WW/TX, HH/TY, BATCH);
    dw_kernel<<<gdw, 256, smem>>>(Wq2, Wkv2);

    attn_kernel<<<1, 256>>>(Wout, temp);

    pw_kernel<DIM><<<gpw, 256>>>(v, meff, out, DIM*DIM);
}

// round 2
// speedup vs baseline: 1.1263x; 1.1263x over previous
#include <cuda_runtime.h>
#include <math.h>

#define BATCH 2
#define DIM   48
#define HEADS 8
#define CPH   6
#define HH    384
#define WW    384
#define NPIX  (HH*WW)

// ---------------- scratch ----------------
__device__ float g_pwq [BATCH*DIM*NPIX];      // 56.6 MB
__device__ float g_pwkv[BATCH*2*DIM*NPIX];    // 113 MB (k: ch 0..47, v: ch 48..95)
__device__ float g_acc [BATCH*HEADS*48];      // 36 Gram + 6 |q|^2 + 6 |k|^2
__device__ float g_meff[BATCH*DIM*DIM];

// ---------------- packed f32x2 ----------------
__device__ __forceinline__ unsigned long long pk2(float lo, float hi){
    unsigned long long r;
    asm("mov.b64 %0, {%1,%2};" : "=l"(r) : "f"(lo), "f"(hi));
    return r;
}
__device__ __forceinline__ void fma2(unsigned long long &d,
                                     unsigned long long a,
                                     unsigned long long b){
    asm("fma.rn.f32x2 %0, %1, %2, %3;" : "=l"(d) : "l"(a), "l"(b), "l"(d));
}
__device__ __forceinline__ float2 unpk(unsigned long long v){
    float lo, hi;
    asm("mov.b64 {%0,%1}, %2;" : "=f"(lo), "=f"(hi) : "l"(v));
    return make_float2(lo, hi);
}

// safe 3-col row load (clamped addresses, predicated value)
__device__ __forceinline__ void row3(float* r, const float* rowp, int x, int xl, int xr,
                                     bool xm, bool xp, bool yok){
    r[0] = (yok && xm) ? __ldg(rowp + xl) : 0.f;
    r[1] =  yok        ? __ldg(rowp + x ) : 0.f;
    r[2] = (yok && xp) ? __ldg(rowp + xr) : 0.f;
}

#define CONV9(s, w, a, b_, c) \
    s = w[0]*a[0]+w[1]*a[1]+w[2]*a[2] \
      + w[3]*b_[0]+w[4]*b_[1]+w[5]*b_[2] \
      + w[6]*c[0]+w[7]*c[1]+w[8]*c[2];

// ---------------- kernels ----------------
__global__ void zero_acc_kernel(){
    int t = blockIdx.x*blockDim.x + threadIdx.x;
    if (t < BATCH*HEADS*48) g_acc[t] = 0.f;
}

// 1x1 conv as GEMM, 48 out-channels, 256 px/block (8 px/thread).
// in index: b*inBC*NPIX + ic*NPIX + px ; out index: b*outBC*NPIX + oc*NPIX + px
__global__ __launch_bounds__(256, 2) void pw8_kernel(const float* __restrict__ in,
                                                     const float* __restrict__ W,
                                                     float* __restrict__ out,
                                                     int inBC, int outBC){
    __shared__ unsigned long long ws[DIM*DIM];   // 18 KB
    const int b = blockIdx.y;
    for (int t = threadIdx.x; t < DIM*DIM; t += 256){
        float w = W[t];
        ws[t] = pk2(w, w);
    }
    __syncthreads();

    const int tid = threadIdx.x;
    const int pxq = tid & 31;
    const int ocg = tid >> 5;           // 8 warps x 6 oc
    const int base = blockIdx.x*256 + pxq*8;
    const float* inp = in + (size_t)b*inBC*NPIX + base;

    unsigned long long acc[CPH][4];
    #pragma unroll
    for (int j = 0; j < CPH; j++){
        acc[j][0]=0ull; acc[j][1]=0ull; acc[j][2]=0ull; acc[j][3]=0ull;
    }

    #pragma unroll 4
    for (int ic = 0; ic < DIM; ic++){
        const float4* ip4 = reinterpret_cast<const float4*>(inp + (size_t)ic*NPIX);
        float4 xa = ip4[0];
        float4 xb = ip4[1];
        unsigned long long a01 = pk2(xa.x, xa.y), a23 = pk2(xa.z, xa.w);
        unsigned long long b01 = pk2(xb.x, xb.y), b23 = pk2(xb.z, xb.w);
        #pragma unroll
        for (int j = 0; j < CPH; j++){
            unsigned long long w = ws[(ocg*CPH + j)*DIM + ic];
            fma2(acc[j][0], a01, w);
            fma2(acc[j][1], a23, w);
            fma2(acc[j][2], b01, w);
            fma2(acc[j][3], b23, w);
        }
    }

    float* op = out + (size_t)b*outBC*NPIX + base;
    #pragma unroll
    for (int j = 0; j < CPH; j++){
        float* o = op + (size_t)(ocg*CPH + j)*NPIX;
        float2 l0 = unpk(acc[j][0]), h0 = unpk(acc[j][1]);
        float2 l1 = unpk(acc[j][2]), h1 = unpk(acc[j][3]);
        *reinterpret_cast<float4*>(o)     = make_float4(l0.x, l0.y, h0.x, h0.y);
        *reinterpret_cast<float4*>(o + 4) = make_float4(l1.x, l1.y, h1.x, h1.y);
    }
}

// q,k depthwise 3x3 + Gram/norm reduction. One head per warp over a 32x8 strip.
// grid (WW/32, HH/64, BATCH*HEADS), block 256.
__global__ __launch_bounds__(256, 2) void qk_gram_kernel(const float* __restrict__ Wq2,
                                                         const float* __restrict__ Wkv2){
    __shared__ float wq[CPH*9], wk[CPH*9];
    __shared__ float accs[48];
    const int tid = threadIdx.x;
    const int bh  = blockIdx.z;
    const int b   = bh >> 3, h = bh & 7;
    if (tid < CPH*9){
        int c6 = tid/9, t = tid%9;
        wq[tid] = Wq2 [(h*CPH + c6)*27 + 9 + t];
        wk[tid] = Wkv2[(h*CPH + c6)*27 + 9 + t];
    }
    if (tid < 48) accs[tid] = 0.f;
    __syncthreads();

    const int lane = tid & 31;
    const int w    = tid >> 5;
    const int x    = blockIdx.x*32 + lane;
    const int yb   = blockIdx.y*64 + w*8;
    const int  xl = max(x-1, 0), xr = min(x+1, WW-1);
    const bool xm = (x > 0),     xp = (x < WW-1);

    const float* qbase = g_pwq  + (size_t)b*DIM*NPIX   + (size_t)h*CPH*NPIX;
    const float* kbase = g_pwkv + (size_t)b*2*DIM*NPIX + (size_t)h*CPH*NPIX;

    float ka[CPH][8];
    float kn[CPH], qn[CPH], G[36];
    #pragma unroll
    for (int i = 0; i < 36; i++) G[i] = 0.f;

    // ---- k channels ----
    #pragma unroll
    for (int c6 = 0; c6 < CPH; c6++){
        const float* p = kbase + (size_t)c6*NPIX;
        float wr[9];
        #pragma unroll
        for (int t = 0; t < 9; t++) wr[t] = wk[c6*9 + t];
        float r0[3], r1[3], r2[3];
        { bool yok = (yb-1 >= 0); row3(r0, p + (yok ? (yb-1) : 0)*WW, x, xl, xr, xm, xp, yok); }
        row3(r1, p + yb*WW, x, xl, xr, xm, xp, true);
        float nrm = 0.f;
        #pragma unroll
        for (int i = 0; i < 8; i++){
            int yy = yb + i + 1; bool yok = (yy < HH);
            row3(r2, p + (yok ? yy : 0)*WW, x, xl, xr, xm, xp, yok);
            float s; CONV9(s, wr, r0, r1, r2);
            ka[c6][i] = s; nrm += s*s;
            r0[0]=r1[0]; r0[1]=r1[1]; r0[2]=r1[2];
            r1[0]=r2[0]; r1[1]=r2[1]; r1[2]=r2[2];
        }
        kn[c6] = nrm;
    }

    // ---- q channels: accumulate Gram per row ----
    #pragma unroll
    for (int c6 = 0; c6 < CPH; c6++){
        const float* p = qbase + (size_t)c6*NPIX;
        float wr[9];
        #pragma unroll
        for (int t = 0; t < 9; t++) wr[t] = wq[c6*9 + t];
        float r0[3], r1[3], r2[3];
        { bool yok = (yb-1 >= 0); row3(r0, p + (yok ? (yb-1) : 0)*WW, x, xl, xr, xm, xp, yok); }
        row3(r1, p + yb*WW, x, xl, xr, xm, xp, true);
        float nrm = 0.f;
        #pragma unroll
        for (int i = 0; i < 8; i++){
            int yy = yb + i + 1; bool yok = (yy < HH);
            row3(r2, p + (yok ? yy : 0)*WW, x, xl, xr, xm, xp, yok);
            float s; CONV9(s, wr, r0, r1, r2);
            nrm += s*s;
            #pragma unroll
            for (int d6 = 0; d6 < CPH; d6++)
                G[c6*CPH + d6] += s * ka[d6][i];
            r0[0]=r1[0]; r0[1]=r1[1]; r0[2]=r1[2];
            r1[0]=r2[0]; r1[1]=r2[1]; r1[2]=r2[2];
        }
        qn[c6] = nrm;
    }

    // ---- reduce: lanes -> warp, warps -> smem, block -> global ----
    #pragma unroll
    for (int j = 0; j < 36; j++){
        float v = G[j];
        #pragma unroll
        for (int o = 16; o; o >>= 1) v += __shfl_xor_sync(0xffffffffu, v, o);
        if (lane == 0) atomicAdd(&accs[j], v);
    }
    #pragma unroll
    for (int j = 0; j < CPH; j++){
        float v = qn[j];
        #pragma unroll
        for (int o = 16; o; o >>= 1) v += __shfl_xor_sync(0xffffffffu, v, o);
        if (lane == 0) atomicAdd(&accs[36 + j], v);
        float u = kn[j];
        #pragma unroll
        for (int o = 16; o; o >>= 1) u += __shfl_xor_sync(0xffffffffu, u, o);
        if (lane == 0) atomicAdd(&accs[42 + j], u);
    }
    __syncthreads();
    if (tid < 48) atomicAdd(&g_acc[(b*HEADS + h)*48 + tid], accs[tid]);
}

// softmax + fold Wout -> Meff[b] (48x48)
__global__ void attn_kernel(const float* __restrict__ Wout,
                            const float* __restrict__ temp){
    __shared__ float attn_s[BATCH*HEADS*36];
    int t = threadIdx.x;
    if (t < BATCH*HEADS*CPH){
        int b  = t/(HEADS*CPH);
        int h  = (t/CPH)%HEADS;
        int c6 = t%CPH;
        const float* a = g_acc + (b*HEADS + h)*48;
        float qnorm = fmaxf(sqrtf(a[36 + c6]), 1e-12f);
        float s[CPH];
        float mx = -1e30f;
        #pragma unroll
        for (int d6 = 0; d6 < CPH; d6++){
            float knorm = fmaxf(sqrtf(a[42 + d6]), 1e-12f);
            float v = a[c6*CPH + d6] / (qnorm*knorm) * temp[h];
            s[d6] = v; mx = fmaxf(mx, v);
        }
        float sum = 0.f;
        #pragma unroll
        for (int d6 = 0; d6 < CPH; d6++){ s[d6] = expf(s[d6]-mx); sum += s[d6]; }
        float inv = 1.f/sum;
        #pragma unroll
        for (int d6 = 0; d6 < CPH; d6++)
            attn_s[(b*HEADS + h)*36 + c6*CPH + d6] = s[d6]*inv;
    }
    __syncthreads();
    for (int e = t; e < BATCH*DIM*DIM; e += blockDim.x){
        int b = e/(DIM*DIM), rem = e%(DIM*DIM), o = rem/DIM, d = rem%DIM;
        int h = d/CPH, d6 = d%CPH;
        float s = 0.f;
        #pragma unroll
        for (int c6 = 0; c6 < CPH; c6++)
            s += Wout[o*DIM + h*CPH + c6] * attn_s[(b*HEADS + h)*36 + c6*CPH + d6];
        g_meff[e] = s;
    }
}

// fused: v = dw3x3(pwkv_hi) computed into smem tile, then out = Meff[b] * v.
// grid (WW/32, HH/8, BATCH), block 256 (8 warps x 6 channels / 6 oc).
__global__ __launch_bounds__(256, 3) void vout_kernel(const float* __restrict__ Wkv2,
                                                      float* __restrict__ out){
    extern __shared__ char smraw[];
    unsigned long long* wm = reinterpret_cast<unsigned long long*>(smraw);      // 48*48 u64
    float* v_s = reinterpret_cast<float*>(smraw + DIM*DIM*8);                   // 48*256 f32
    float* wv  = v_s + DIM*256;                                                 // 48*9 f32

    const int tid = threadIdx.x;
    const int b   = blockIdx.z;
    for (int t = tid; t < DIM*DIM; t += 256){
        float m = g_meff[b*DIM*DIM + t];
        wm[t] = pk2(m, m);
    }
    for (int t = tid; t < DIM*9; t += 256)
        wv[t] = Wkv2[(DIM + t/9)*27 + 9 + (t%9)];
    __syncthreads();

    const int lane = tid & 31;
    const int w    = tid >> 5;
    const int x0   = blockIdx.x*32;
    const int x    = x0 + lane;
    const int yb   = blockIdx.y*8;
    const int  xl = max(x-1, 0), xr = min(x+1, WW-1);
    const bool xm = (x > 0),     xp = (x < WW-1);

    // phase 1: depthwise v for channels w*6 .. w*6+5 over 32x8 tile
    const float* vbase = g_pwkv + (size_t)b*2*DIM*NPIX + (size_t)DIM*NPIX;
    #pragma unroll
    for (int c6 = 0; c6 < CPH; c6++){
        int c = w*CPH + c6;
        const float* p = vbase + (size_t)c*NPIX;
        float wr[9];
        #pragma unroll
        for (int t = 0; t < 9; t++) wr[t] = wv[c*9 + t];
        float r0[3], r1[3], r2[3];
        { bool yok = (yb-1 >= 0); row3(r0, p + (yok ? (yb-1) : 0)*WW, x, xl, xr, xm, xp, yok); }
        row3(r1, p + yb*WW, x, xl, xr, xm, xp, true);
        #pragma unroll
        for (int i = 0; i < 8; i++){
            int yy = yb + i + 1; bool yok = (yy < HH);
            row3(r2, p + (yok ? yy : 0)*WW, x, xl, xr, xm, xp, yok);
            float s; CONV9(s, wr, r0, r1, r2);
            v_s[c*256 + i*32 + lane] = s;
            r0[0]=r1[0]; r0[1]=r1[1]; r0[2]=r1[2];
            r1[0]=r2[0]; r1[1]=r2[1]; r1[2]=r2[2];
        }
    }
    __syncthreads();

    // phase 2: out[oc, px] = sum_d Meff[oc][d] * v_s[d][px]; warp w -> oc w*6..+5
    unsigned long long acc[CPH][4];
    #pragma unroll
    for (int j = 0; j < CPH; j++){
        acc[j][0]=0ull; acc[j][1]=0ull; acc[j][2]=0ull; acc[j][3]=0ull;
    }
    #pragma unroll 4
    for (int d = 0; d < DIM; d++){
        const float4* vp = reinterpret_cast<const float4*>(v_s + d*256);
        float4 a  = vp[lane];          // px 4*lane .. 4*lane+3
        float4 bq = vp[lane + 32];     // px 128+4*lane ..
        unsigned long long a01 = pk2(a.x,  a.y ), a23 = pk2(a.z,  a.w );
        unsigned long long b01 = pk2(bq.x, bq.y), b23 = pk2(bq.z, bq.w);
        #pragma unroll
        for (int j = 0; j < CPH; j++){
            unsigned long long ww = wm[(w*CPH + j)*DIM + d];
            fma2(acc[j][0], a01, ww);
            fma2(acc[j][1], a23, ww);
            fma2(acc[j][2], b01, ww);
            fma2(acc[j][3], b23, ww);
        }
    }

    #pragma unroll
    for (int j = 0; j < CPH; j++){
        int oc = w*CPH + j;
        float* op = out + ((size_t)(b*DIM + oc))*NPIX;
        int px0 = 4*lane;
        int px1 = 128 + 4*lane;
        float2 l0 = unpk(acc[j][0]), h0 = unpk(acc[j][1]);
        float2 l1 = unpk(acc[j][2]), h1 = unpk(acc[j][3]);
        *reinterpret_cast<float4*>(op + (size_t)(yb + (px0>>5))*WW + x0 + (px0&31)) =
            make_float4(l0.x, l0.y, h0.x, h0.y);
        *reinterpret_cast<float4*>(op + (size_t)(yb + (px1>>5))*WW + x0 + (px1&31)) =
            make_float4(l1.x, l1.y, h1.x, h1.y);
    }
}

// ---------------- launch ----------------
extern "C" void kernel_launch(void* const* d_in, const int* in_sizes, int n_in,
                              void* d_out, int out_size){
    const float* img  = (const float*)d_in[0];
    const float* evs  = (const float*)d_in[1];
    const float* Wq1  = (const float*)d_in[2];
    const float* Wq2  = (const float*)d_in[3];
    const float* Wkv1 = (const float*)d_in[4];
    const float* Wkv2 = (const float*)d_in[5];
    const float* Wout = (const float*)d_in[6];
    const float* temp = (const float*)d_in[7];
    float* out = (float*)d_out;

    float *pwq, *pwkv;
    cudaGetSymbolAddress((void**)&pwq,  g_pwq);
    cudaGetSymbolAddress((void**)&pwkv, g_pwkv);

    size_t smem_vout = (size_t)DIM*DIM*8 + (size_t)DIM*256*4 + (size_t)DIM*9*4; // 69312
    cudaFuncSetAttribute(vout_kernel, cudaFuncAttributeMaxDynamicSharedMemorySize, (int)smem_vout);

    zero_acc_kernel<<<3, 256>>>();

    dim3 gpw(NPIX/256, BATCH);
    pw8_kernel<<<gpw, 256>>>(evs, Wq1,            pwq,             DIM,   DIM);
    pw8_kernel<<<gpw, 256>>>(img, Wkv1,           pwkv,            DIM, 2*DIM);
    pw8_kernel<<<gpw, 256>>>(img, Wkv1 + DIM*DIM, pwkv + (size_t)DIM*NPIX, DIM, 2*DIM);

    dim3 gqk(WW/32, HH/64, BATCH*HEADS);
    qk_gram_kernel<<<gqk, 256>>>(Wq2, Wkv2);

    attn_kernel<<<1, 256>>>(Wout, temp);

    dim3 gvo(WW/32, HH/8, BATCH);
    vout_kernel<<<gvo, 256, smem_vout>>>(Wkv2, out);
}